// round 2
// baseline (speedup 1.0000x reference)
#include <cuda_runtime.h>
#include <cstdint>

#define B_DIM 2048
#define I_DIM 512
#define O_DIM 512

#define BM 64
#define BN 64
#define BK 16
#define NTHREADS 256

// Scratch for precomputed A = 1 - w*s, B = w*(2s-1)   (allocation-free __device__ globals)
__device__ float g_A[I_DIM * O_DIM];
__device__ float g_B[I_DIM * O_DIM];

// ---------- packed f32x2 helpers (sm_100+ FFMA2/FMUL2 via PTX) ----------
__device__ __forceinline__ unsigned long long pack2(float lo, float hi) {
    unsigned long long r;
    asm("mov.b64 %0, {%1, %2};" : "=l"(r) : "f"(lo), "f"(hi));
    return r;
}
__device__ __forceinline__ void unpack2(unsigned long long v, float& lo, float& hi) {
    asm("mov.b64 {%0, %1}, %2;" : "=f"(lo), "=f"(hi) : "l"(v));
}
__device__ __forceinline__ unsigned long long fma2(unsigned long long a, unsigned long long b,
                                                   unsigned long long c) {
    unsigned long long d;
    asm("fma.rn.f32x2 %0, %1, %2, %3;" : "=l"(d) : "l"(a), "l"(b), "l"(c));
    return d;
}
__device__ __forceinline__ unsigned long long mul2(unsigned long long a, unsigned long long b) {
    unsigned long long d;
    asm("mul.rn.f32x2 %0, %1, %2;" : "=l"(d) : "l"(a), "l"(b));
    return d;
}

// ---------- prep: sigmoid + algebraic refactor ----------
__global__ void prep_kernel(const float* __restrict__ wl, const float* __restrict__ sl) {
    int idx = blockIdx.x * blockDim.x + threadIdx.x;
    if (idx < I_DIM * O_DIM) {
        float w = 1.0f / (1.0f + __expf(-wl[idx]));
        float s = 1.0f / (1.0f + __expf(-sl[idx]));
        g_A[idx] = 1.0f - w * s;          // factor = A + x*B
        g_B[idx] = w * (2.0f * s - 1.0f);
    }
}

// ---------- main: product-GEMM, 64x64 tile, 4x4 microtile, f32x2 packed ----------
__global__ __launch_bounds__(NTHREADS, 2)
void fuzzy_prod_kernel(const float* __restrict__ X, float* __restrict__ OUT) {
    __shared__ float Xs[2][BK][BM];
    __shared__ float As[2][BK][BN];
    __shared__ float Bs[2][BK][BN];

    const int tid = threadIdx.x;
    const int tx  = tid & 15;      // o-direction, 16 threads
    const int ty  = tid >> 4;      // b-direction, 16 threads
    const int bn0 = blockIdx.x * BN;
    const int bm0 = blockIdx.y * BM;

    // loader mapping for X tile: 64 rows x 16 k  -> 1 float4 per thread
    const int xrow = tid >> 2;           // 0..63
    const int xc4  = (tid & 3) * 4;      // 0,4,8,12
    // loader mapping for A/B tiles: 16 k-rows x 64 o -> 1 float4 per thread each
    const int arow = tid >> 4;           // 0..15
    const int acol = (tid & 15) * 4;     // 0..60

    const unsigned long long ONE2 = pack2(1.0f, 1.0f);
    unsigned long long acc[4][2];
#pragma unroll
    for (int m = 0; m < 4; m++) { acc[m][0] = ONE2; acc[m][1] = ONE2; }

    // prologue: fill buffer 0
    {
        float4 xv = *(const float4*)&X[(bm0 + xrow) * I_DIM + 0 + xc4];
        float4 av = *(const float4*)&g_A[(0 + arow) * O_DIM + bn0 + acol];
        float4 bv = *(const float4*)&g_B[(0 + arow) * O_DIM + bn0 + acol];
        Xs[0][xc4 + 0][xrow] = xv.x;
        Xs[0][xc4 + 1][xrow] = xv.y;
        Xs[0][xc4 + 2][xrow] = xv.z;
        Xs[0][xc4 + 3][xrow] = xv.w;
        *(float4*)&As[0][arow][acol] = av;
        *(float4*)&Bs[0][arow][acol] = bv;
    }
    __syncthreads();

    int buf = 0;
    for (int kt = 0; kt < I_DIM; kt += BK) {
        const int nxt = buf ^ 1;
        const bool has_next = (kt + BK < I_DIM);
        float4 xn, an, bn_;
        if (has_next) {  // register-staged prefetch (LDG overlaps compute)
            xn  = *(const float4*)&X[(bm0 + xrow) * I_DIM + (kt + BK) + xc4];
            an  = *(const float4*)&g_A[(kt + BK + arow) * O_DIM + bn0 + acol];
            bn_ = *(const float4*)&g_B[(kt + BK + arow) * O_DIM + bn0 + acol];
        }

#pragma unroll
        for (int k = 0; k < BK; k++) {
            float4 xv = *(const float4*)&Xs[buf][k][ty * 4];
            float4 av = *(const float4*)&As[buf][k][tx * 4];
            float4 bv = *(const float4*)&Bs[buf][k][tx * 4];
            unsigned long long a01 = pack2(av.x, av.y);
            unsigned long long a23 = pack2(av.z, av.w);
            unsigned long long b01 = pack2(bv.x, bv.y);
            unsigned long long b23 = pack2(bv.z, bv.w);
            float xm[4] = {xv.x, xv.y, xv.z, xv.w};
#pragma unroll
            for (int m = 0; m < 4; m++) {
                unsigned long long x2 = pack2(xm[m], xm[m]);
                acc[m][0] = mul2(acc[m][0], fma2(x2, b01, a01));
                acc[m][1] = mul2(acc[m][1], fma2(x2, b23, a23));
            }
        }

        if (has_next) {
            Xs[nxt][xc4 + 0][xrow] = xn.x;
            Xs[nxt][xc4 + 1][xrow] = xn.y;
            Xs[nxt][xc4 + 2][xrow] = xn.z;
            Xs[nxt][xc4 + 3][xrow] = xn.w;
            *(float4*)&As[nxt][arow][acol] = an;
            *(float4*)&Bs[nxt][arow][acol] = bn_;
        }
        __syncthreads();
        buf = nxt;
    }

    // epilogue
#pragma unroll
    for (int m = 0; m < 4; m++) {
        float4 o4;
        unpack2(acc[m][0], o4.x, o4.y);
        unpack2(acc[m][1], o4.z, o4.w);
        *(float4*)&OUT[(bm0 + ty * 4 + m) * O_DIM + bn0 + tx * 4] = o4;
    }
}

extern "C" void kernel_launch(void* const* d_in, const int* in_sizes, int n_in,
                              void* d_out, int out_size) {
    const float* x  = (const float*)d_in[0];   // (2048, 512)
    const float* wl = (const float*)d_in[1];   // (512, 512)
    const float* sl = (const float*)d_in[2];   // (512, 512)
    float* out = (float*)d_out;                // (2048, 512)

    prep_kernel<<<(I_DIM * O_DIM + 255) / 256, 256>>>(wl, sl);

    dim3 grid(O_DIM / BN, B_DIM / BM);  // (8, 32) = 256 CTAs
    fuzzy_prod_kernel<<<grid, NTHREADS>>>(x, out);
}

// round 3
// speedup vs baseline: 1.1208x; 1.1208x over previous
#include <cuda_runtime.h>
#include <cstdint>

#define B_DIM 2048
#define I_DIM 512
#define O_DIM 512

#define BM 64
#define BN 64
#define BK 16
#define NTHREADS 256

// Scratch for precomputed A = 1 - w*s, B = w*(2s-1)
__device__ float g_A[I_DIM * O_DIM];
__device__ float g_B[I_DIM * O_DIM];

// ---------- packed f32x2 helpers (sm_100+ FFMA2/FMUL2 via PTX) ----------
__device__ __forceinline__ unsigned long long pack2(float lo, float hi) {
    unsigned long long r;
    asm("mov.b64 %0, {%1, %2};" : "=l"(r) : "f"(lo), "f"(hi));
    return r;
}
__device__ __forceinline__ void unpack2(unsigned long long v, float& lo, float& hi) {
    asm("mov.b64 {%0, %1}, %2;" : "=f"(lo), "=f"(hi) : "l"(v));
}
__device__ __forceinline__ unsigned long long fma2(unsigned long long a, unsigned long long b,
                                                   unsigned long long c) {
    unsigned long long d;
    asm("fma.rn.f32x2 %0, %1, %2, %3;" : "=l"(d) : "l"(a), "l"(b), "l"(c));
    return d;
}
__device__ __forceinline__ unsigned long long mul2(unsigned long long a, unsigned long long b) {
    unsigned long long d;
    asm("mul.rn.f32x2 %0, %1, %2;" : "=l"(d) : "l"(a), "l"(b));
    return d;
}

// ---------- prep: sigmoid + algebraic refactor ----------
__global__ void prep_kernel(const float* __restrict__ wl, const float* __restrict__ sl) {
    int idx = blockIdx.x * blockDim.x + threadIdx.x;
    if (idx < I_DIM * O_DIM) {
        float w = 1.0f / (1.0f + __expf(-wl[idx]));
        float s = 1.0f / (1.0f + __expf(-sl[idx]));
        g_A[idx] = 1.0f - w * s;          // factor = A + x*B
        g_B[idx] = w * (2.0f * s - 1.0f);
    }
}

// ---------- main: product-GEMM, 64x64 tile, 8x2 microtile, b-pair packing ----------
__global__ __launch_bounds__(NTHREADS, 2)
void fuzzy_prod_kernel(const float* __restrict__ X, float* __restrict__ OUT) {
    // Xs stored k-major with XOR swizzle on the b index (groups of 8 floats):
    //   element (k, b) lives at Xs[k][ b ^ (8 * ((k>>2)&3)) ]
    // -> conflict-free transpose stores AND broadcast float4 main-loop reads.
    __shared__ float Xs[2][BK][BM];
    __shared__ float As[2][BK][BN];
    __shared__ float Bs[2][BK][BN];

    const int tid = threadIdx.x;
    const int tx  = tid & 31;      // o-pair index: this thread owns o = tx*2, tx*2+1
    const int ty  = tid >> 5;      // b-octet: this thread owns b = ty*8 .. ty*8+7
    const int bn0 = blockIdx.x * BN;
    const int bm0 = blockIdx.y * BM;

    // loader mapping: X tile 64 rows x 16 k -> 1 float4 per thread
    const int xrow = tid >> 2;           // 0..63  (b)
    const int xc4  = (tid & 3) * 4;      // 0,4,8,12 (k base)
    const int xq   = (tid & 3);          // == (k>>2)&3 for this thread's 4 k's
    // loader mapping: A/B tiles 16 k-rows x 64 o -> 1 float4 per thread each
    const int arow = tid >> 4;           // 0..15
    const int acol = (tid & 15) * 4;     // 0..60

    const unsigned long long ONE2 = pack2(1.0f, 1.0f);
    // acc[p][o]: packed pair of b-rows (ty*8+2p, ty*8+2p+1) for column tx*2+o
    unsigned long long acc[4][2];
#pragma unroll
    for (int p = 0; p < 4; p++) { acc[p][0] = ONE2; acc[p][1] = ONE2; }

    // prologue: fill buffer 0
    {
        float4 xv = *(const float4*)&X[(bm0 + xrow) * I_DIM + xc4];
        float4 av = *(const float4*)&g_A[arow * O_DIM + bn0 + acol];
        float4 bv = *(const float4*)&g_B[arow * O_DIM + bn0 + acol];
        const int swb = xrow ^ (8 * xq);
        Xs[0][xc4 + 0][swb] = xv.x;
        Xs[0][xc4 + 1][swb] = xv.y;
        Xs[0][xc4 + 2][swb] = xv.z;
        Xs[0][xc4 + 3][swb] = xv.w;
        *(float4*)&As[0][arow][acol] = av;
        *(float4*)&Bs[0][arow][acol] = bv;
    }
    __syncthreads();

    int buf = 0;
    for (int kt = 0; kt < I_DIM; kt += BK) {
        const int nxt = buf ^ 1;
        const bool has_next = (kt + BK < I_DIM);
        float4 xn, an, bn_;
        if (has_next) {  // register-staged prefetch overlaps compute
            xn  = *(const float4*)&X[(bm0 + xrow) * I_DIM + (kt + BK) + xc4];
            an  = *(const float4*)&g_A[(kt + BK + arow) * O_DIM + bn0 + acol];
            bn_ = *(const float4*)&g_B[(kt + BK + arow) * O_DIM + bn0 + acol];
        }

#pragma unroll
        for (int k = 0; k < BK; k++) {
            const int q   = (k >> 2) & 3;
            const int xb  = (ty ^ q) * 8;            // swizzled base of this thread's 8 b's
            float4 x0 = *(const float4*)&Xs[buf][k][xb];      // broadcast within warp
            float4 x1 = *(const float4*)&Xs[buf][k][xb + 4];  // broadcast within warp
            float2 a  = *(const float2*)&As[buf][k][tx * 2];
            float2 b  = *(const float2*)&Bs[buf][k][tx * 2];

            // b-pairs come register-adjacent from the float4 -> packs are free
            unsigned long long xp0 = pack2(x0.x, x0.y);
            unsigned long long xp1 = pack2(x0.z, x0.w);
            unsigned long long xp2 = pack2(x1.x, x1.y);
            unsigned long long xp3 = pack2(x1.z, x1.w);
            // duplicate A/B scalars across the packed pair (4 movs per k)
            unsigned long long a0d = pack2(a.x, a.x);
            unsigned long long a1d = pack2(a.y, a.y);
            unsigned long long b0d = pack2(b.x, b.x);
            unsigned long long b1d = pack2(b.y, b.y);

            acc[0][0] = mul2(acc[0][0], fma2(xp0, b0d, a0d));
            acc[0][1] = mul2(acc[0][1], fma2(xp0, b1d, a1d));
            acc[1][0] = mul2(acc[1][0], fma2(xp1, b0d, a0d));
            acc[1][1] = mul2(acc[1][1], fma2(xp1, b1d, a1d));
            acc[2][0] = mul2(acc[2][0], fma2(xp2, b0d, a0d));
            acc[2][1] = mul2(acc[2][1], fma2(xp2, b1d, a1d));
            acc[3][0] = mul2(acc[3][0], fma2(xp3, b0d, a0d));
            acc[3][1] = mul2(acc[3][1], fma2(xp3, b1d, a1d));
        }

        if (has_next) {
            const int swb = xrow ^ (8 * xq);
            Xs[nxt][xc4 + 0][swb] = xn.x;
            Xs[nxt][xc4 + 1][swb] = xn.y;
            Xs[nxt][xc4 + 2][swb] = xn.z;
            Xs[nxt][xc4 + 3][swb] = xn.w;
            *(float4*)&As[nxt][arow][acol] = an;
            *(float4*)&Bs[nxt][arow][acol] = bn_;
        }
        __syncthreads();
        buf = nxt;
    }

    // epilogue: 8 coalesced STG.64 per thread
#pragma unroll
    for (int p = 0; p < 4; p++) {
        float r0o0, r1o0, r0o1, r1o1;
        unpack2(acc[p][0], r0o0, r1o0);
        unpack2(acc[p][1], r0o1, r1o1);
        const int row0 = bm0 + ty * 8 + 2 * p;
        float2 v0 = make_float2(r0o0, r0o1);
        float2 v1 = make_float2(r1o0, r1o1);
        *(float2*)&OUT[row0 * O_DIM + bn0 + tx * 2]       = v0;
        *(float2*)&OUT[(row0 + 1) * O_DIM + bn0 + tx * 2] = v1;
    }
}

extern "C" void kernel_launch(void* const* d_in, const int* in_sizes, int n_in,
                              void* d_out, int out_size) {
    const float* x  = (const float*)d_in[0];   // (2048, 512)
    const float* wl = (const float*)d_in[1];   // (512, 512)
    const float* sl = (const float*)d_in[2];   // (512, 512)
    float* out = (float*)d_out;                // (2048, 512)

    prep_kernel<<<(I_DIM * O_DIM + 255) / 256, 256>>>(wl, sl);

    dim3 grid(O_DIM / BN, B_DIM / BM);  // (8, 32) = 256 CTAs
    fuzzy_prod_kernel<<<grid, NTHREADS>>>(x, out);
}